// round 13
// baseline (speedup 1.0000x reference)
#include <cuda_runtime.h>
#include <cstdint>

// ---------------------------------------------------------------------------
// TripletLoss, JAX-exact gumbel semi-hard mining. B=384, D=256, C=48.
//
// JAX (threefry_partitionable) random bits for a float32 tensor of size N:
//     (o0, o1) = threefry2x32(key=(0,42), counter=(n>>32, n&0xffffffff))
//     bits[n]  = o0 ^ o1
// N = B^3 < 2^32 -> counter = (0, n), n = (i*B + p)*B + k.
//
// Single persistent kernel, 144 blocks x 256 threads (one wave):
//   phase 1: enqueue valid (i,p) pairs (labels only) into a global queue;
//            32x32 dist tile per block (2x2 register micro-tiles, float4);
//            also writes -log(dist) so phase 2 never logf's the row.
//   grid sync: generation-counting atomic (replay-safe, no counter reset).
//   phase 2: warp-per-pair from the queue (1152 warps vs ~1.5K pairs):
//            register row scan + ballot compaction, threefry+gumbel only on
//            compacted candidates; warp->block aggregation, 1 atomic/block.
//   last-done block writes out[0], re-zeros accumulators, advances g_qbase.
// ---------------------------------------------------------------------------

#define BB 384
#define DD 256
#define MARGIN 0.2f
#define GRID 144
#define NWARP 8
#define QCAP 131072u   // power of 2, > worst-case pair count (73728)

__device__ float  g_dist[BB * BB];
__device__ float  g_nld[BB * BB];        // -log(dist)
__device__ unsigned g_queue[QCAP];
__device__ double g_total;               // zero-init; re-zeroed each replay
__device__ unsigned int g_count;         // zero-init; re-zeroed each replay
__device__ unsigned int g_qn;            // monotonic across replays
__device__ unsigned int g_qbase;         // start of current replay's queue
__device__ unsigned int g_arrive;        // monotonic grid-sync counter
__device__ unsigned int g_done;          // monotonic done counter

// ---------------- Threefry-2x32-20, key = (0, 42) --------------------------
__device__ __forceinline__ void threefry2x32_42(unsigned c0, unsigned c1,
                                                unsigned& o0, unsigned& o1) {
    const unsigned ks0 = 0u;
    const unsigned ks1 = 42u;
    const unsigned ks2 = 0x1BD11BDAu ^ ks0 ^ ks1;
    unsigned x0 = c0 + ks0;
    unsigned x1 = c1 + ks1;
#define TF_ROUND(R) { x0 += x1; x1 = __funnelshift_l(x1, x1, (R)); x1 ^= x0; }
    TF_ROUND(13) TF_ROUND(15) TF_ROUND(26) TF_ROUND(6)
    x0 += ks1; x1 += ks2 + 1u;
    TF_ROUND(17) TF_ROUND(29) TF_ROUND(16) TF_ROUND(24)
    x0 += ks2; x1 += ks0 + 2u;
    TF_ROUND(13) TF_ROUND(15) TF_ROUND(26) TF_ROUND(6)
    x0 += ks0; x1 += ks1 + 3u;
    TF_ROUND(17) TF_ROUND(29) TF_ROUND(16) TF_ROUND(24)
    x0 += ks1; x1 += ks2 + 4u;
    TF_ROUND(13) TF_ROUND(15) TF_ROUND(26) TF_ROUND(6)
    x0 += ks2; x1 += ks0 + 5u;
#undef TF_ROUND
    o0 = x0; o1 = x1;
}

// jax uniform(tiny,1): f = bitcast((bits>>9)|0x3f800000)-1; u = max(f,tiny);
// gumbel = -log(-log(u)). Accurate logf (selection-critical near u->1).
__device__ __forceinline__ float gumbel_from_bits(unsigned bits) {
    const float tiny = 1.17549435e-38f;
    float f = __uint_as_float((bits >> 9) | 0x3f800000u) - 1.0f;
    float u = fmaxf(f, tiny);
    return -logf(-logf(u));
}

struct SmemP1 {
    float shA[32][33];
    float shB[32][33];
};
struct SmemP2 {
    int    s_lab[BB];
    int    buf_k[NWARP][BB];
    float  buf_d[NWARP][BB];
    double s_wsum[NWARP];
    unsigned s_wcnt[NWARP];
};

__global__ __launch_bounds__(256) void triplet_fused(const float* __restrict__ feat,
                                                     const int*   __restrict__ labels,
                                                     const int*   __restrict__ epoch_p,
                                                     float*       __restrict__ out) {
    __shared__ union { SmemP1 p1; SmemP2 p2; } sm;
    const int t    = threadIdx.x;
    const int wid  = t >> 5;
    const int lane = t & 31;

    // ---------------- phase 1a: enqueue valid (i,p) pairs ------------------
    for (int i = blockIdx.x; i < BB; i += GRID) {
        const int labi = labels[i];
        for (int p = i + 1 + t; p < BB; p += 256) {
            if (labels[p] == labi) {
                unsigned idx = atomicAdd(&g_qn, 1u);
                g_queue[idx & (QCAP - 1u)] = ((unsigned)i << 16) | (unsigned)p;
            }
        }
    }

    // ---------------- phase 1b: dist tile (32x32, 2x2 micro-tiles) ---------
    {
        const int bx = blockIdx.x % 12, by = blockIdx.x / 12;
        const int tx = t & 15, ty = t >> 4;
        const int i0 = by * 32, j0 = bx * 32;
        const int lr = t >> 3;
        const int lc = (t & 7) * 4;
        float a00 = 0.f, a01 = 0.f, a10 = 0.f, a11 = 0.f;

        for (int d0 = 0; d0 < DD; d0 += 32) {
            const float4 av = *(const float4*)&feat[(i0 + lr) * DD + d0 + lc];
            const float4 bv = *(const float4*)&feat[(j0 + lr) * DD + d0 + lc];
            sm.p1.shA[lr][lc + 0] = av.x; sm.p1.shA[lr][lc + 1] = av.y;
            sm.p1.shA[lr][lc + 2] = av.z; sm.p1.shA[lr][lc + 3] = av.w;
            sm.p1.shB[lr][lc + 0] = bv.x; sm.p1.shB[lr][lc + 1] = bv.y;
            sm.p1.shB[lr][lc + 2] = bv.z; sm.p1.shB[lr][lc + 3] = bv.w;
            __syncthreads();
#pragma unroll
            for (int kk = 0; kk < 32; ++kk) {
                const float ai0 = sm.p1.shA[2 * ty + 0][kk];
                const float ai1 = sm.p1.shA[2 * ty + 1][kk];
                const float bj0 = sm.p1.shB[2 * tx + 0][kk];
                const float bj1 = sm.p1.shB[2 * tx + 1][kk];
                float d;
                d = ai0 - bj0; a00 = fmaf(d, d, a00);
                d = ai0 - bj1; a01 = fmaf(d, d, a01);
                d = ai1 - bj0; a10 = fmaf(d, d, a10);
                d = ai1 - bj1; a11 = fmaf(d, d, a11);
            }
            __syncthreads();
        }
        const int i = i0 + 2 * ty;
        const int j = j0 + 2 * tx;
        const float d00 = sqrtf(fmaxf(a00, 1e-11f));
        const float d01 = sqrtf(fmaxf(a01, 1e-11f));
        const float d10 = sqrtf(fmaxf(a10, 1e-11f));
        const float d11 = sqrtf(fmaxf(a11, 1e-11f));
        g_dist[(i + 0) * BB + j + 0] = d00;  g_nld[(i + 0) * BB + j + 0] = -logf(d00);
        g_dist[(i + 0) * BB + j + 1] = d01;  g_nld[(i + 0) * BB + j + 1] = -logf(d01);
        g_dist[(i + 1) * BB + j + 0] = d10;  g_nld[(i + 1) * BB + j + 0] = -logf(d10);
        g_dist[(i + 1) * BB + j + 1] = d11;  g_nld[(i + 1) * BB + j + 1] = -logf(d11);
    }

    // ---------------- grid sync (generation counter; replay-safe) ----------
    __syncthreads();
    if (t == 0) {
        __threadfence();
        unsigned old = atomicAdd(&g_arrive, 1u);
        unsigned target = (old / (unsigned)GRID + 1u) * (unsigned)GRID;
        while (atomicAdd(&g_arrive, 0u) < target) __nanosleep(32);
        __threadfence();
    }
    __syncthreads();

    // ---------------- phase 2: warp-per-pair mining -------------------------
    const bool semiMode = (*epoch_p) > 3;
    const unsigned qend   = atomicAdd(&g_qn, 0u);
    const unsigned qstart = atomicAdd(&g_qbase, 0u);
    const unsigned npairs = qend - qstart;

    for (int k = t; k < BB; k += 256) sm.p2.s_lab[k] = labels[k];
    __syncthreads();

    double   lsum = 0.0;
    unsigned lcnt = 0u;
    const unsigned gw = (unsigned)blockIdx.x * NWARP + (unsigned)wid;

    for (unsigned off = gw; off < npairs; off += (unsigned)GRID * NWARP) {
        const unsigned q = g_queue[(qstart + off) & (QCAP - 1u)];
        const int i = (int)(q >> 16);
        const int p = (int)(q & 0xffffu);
        const float* __restrict__ drow = g_dist + i * BB;
        const float* __restrict__ nrow = g_nld  + i * BB;
        const int   labi = sm.p2.s_lab[i];
        const float dp   = drow[p];
        const float dhi  = dp + MARGIN;
        const unsigned nbase = ((unsigned)i * BB + (unsigned)p) * (unsigned)BB;

        // row into registers (MLP=12)
        float dk[12];
#pragma unroll
        for (int tile = 0; tile < 12; ++tile) dk[tile] = drow[tile * 32 + lane];

        // mask scan + ballot compaction (ascending k order preserved)
        int cnt = 0;
#pragma unroll
        for (int tile = 0; tile < 12; ++tile) {
            const int k = tile * 32 + lane;
            bool s;
            if (semiMode) s = (sm.p2.s_lab[k] != labi) && (dk[tile] > dp) && (dk[tile] < dhi);
            else          s = (sm.p2.s_lab[k] != labi);
            const unsigned bal = __ballot_sync(0xffffffffu, s);
            if (s) {
                int pos = cnt + __popc(bal & ((1u << lane) - 1u));
                sm.p2.buf_k[wid][pos] = k;
                sm.p2.buf_d[wid][pos] = dk[tile];
            }
            cnt += __popc(bal);
        }

        // score compacted candidates (lane-strided ascending k:
        // strict '>' keeps first max per lane)
        float best = -3.4e38f;
        int   bk   = 0;
        float bd   = 0.0f;
        for (int c = lane; c < cnt; c += 32) {
            const int   k   = sm.p2.buf_k[wid][c];
            const float dkc = sm.p2.buf_d[wid][c];
            unsigned o0, o1;
            threefry2x32_42(0u, nbase + (unsigned)k, o0, o1);
            float sc = (semiMode ? nrow[k] : 0.0f) + gumbel_from_bits(o0 ^ o1);
            if (sc > best) { best = sc; bk = k; bd = dkc; }
        }
        // warp argmax, lowest-index tie-break (matches jnp.argmax)
#pragma unroll
        for (int o = 16; o > 0; o >>= 1) {
            float ov = __shfl_down_sync(0xffffffffu, best, o);
            int   ok = __shfl_down_sync(0xffffffffu, bk,   o);
            float od = __shfl_down_sync(0xffffffffu, bd,   o);
            if (ov > best || (ov == best && ok < bk)) { best = ov; bk = ok; bd = od; }
        }
        if (lane == 0 && cnt > 0) {
            lsum += (double)fmaxf(dp - bd + MARGIN, 0.0f);
            lcnt += 1u;
        }
    }

    // ---------------- block aggregation + last-done epilogue ---------------
    if (lane == 0) { sm.p2.s_wsum[wid] = lsum; sm.p2.s_wcnt[wid] = lcnt; }
    __syncthreads();
    if (t == 0) {
        double   bs = 0.0;
        unsigned bc = 0u;
#pragma unroll
        for (int w = 0; w < NWARP; ++w) { bs += sm.p2.s_wsum[w]; bc += sm.p2.s_wcnt[w]; }
        if (bc > 0u) {
            atomicAdd(&g_total, bs);
            atomicAdd(&g_count, bc);
        }
        __threadfence();
        unsigned old = atomicAdd(&g_done, 1u);
        if ((old % (unsigned)GRID) == (unsigned)GRID - 1u) {
            unsigned long long tb = atomicExch((unsigned long long*)&g_total, 0ull);
            double   tot = __longlong_as_double((long long)tb);
            unsigned cnt = atomicExch(&g_count, 0u);
            out[0] = (cnt > 0u) ? (float)(tot / (double)cnt) : 0.0f;
            atomicExch(&g_qbase, qend);      // next replay's queue start
        }
    }
}

extern "C" void kernel_launch(void* const* d_in, const int* in_sizes, int n_in,
                              void* d_out, int out_size) {
    const float* feat   = (const float*)d_in[0];
    const int*   labels = (const int*)d_in[1];
    const int*   epoch  = (const int*)d_in[2];
    float*       out    = (float*)d_out;

    triplet_fused<<<GRID, 256>>>(feat, labels, epoch, out);
}

// round 16
// speedup vs baseline: 2.5750x; 2.5750x over previous
#include <cuda_runtime.h>
#include <cstdint>

// ---------------------------------------------------------------------------
// TripletLoss, JAX-exact gumbel semi-hard mining. B=384, D=256, C=48.
//
// JAX (threefry_partitionable) random bits for a float32 tensor of size N:
//     (o0, o1) = threefry2x32(key=(0,42), counter=(n>>32, n&0xffffffff))
//     bits[n]  = o0 ^ o1
// N = B^3 < 2^32 -> counter = (0, n), n = (i*B + p)*B + k.
//
// Single persistent kernel, 144 blocks x 256 threads (one wave):
//   phase 1: enqueue valid (i,p) pairs (labels only) into a global queue;
//            32x32 dist tile per block (2x2 register micro-tiles, float4);
//            also writes -log(dist).
//   grid sync: generation-counting atomic (replay-safe, no counter reset).
//   phase 2: warp-per-pair from the queue. Queue bounds are read ONCE per
//            block (volatile ld) -- NOT per-thread atomics (R13 lesson:
//            73K same-address returning atomics serialized ~35us in L2).
//            dist+nld rows prefetched to registers, candidates compacted
//            (k, d, nld) to smem; scoring chain has no global loads.
//   last-done block writes out[0], re-zeros accumulators, advances g_qbase.
// ---------------------------------------------------------------------------

#define BB 384
#define DD 256
#define MARGIN 0.2f
#define GRID 144
#define NWARP 8
#define QCAP 131072u   // power of 2, > worst-case pair count (73728)

__device__ float  g_dist[BB * BB];
__device__ float  g_nld[BB * BB];        // -log(dist)
__device__ unsigned g_queue[QCAP];
__device__ double g_total;               // zero-init; re-zeroed each replay
__device__ unsigned int g_count;         // zero-init; re-zeroed each replay
__device__ unsigned int g_qn;            // monotonic across replays
__device__ unsigned int g_qbase;         // start of current replay's queue
__device__ unsigned int g_arrive;        // monotonic grid-sync counter
__device__ unsigned int g_done;          // monotonic done counter

// ---------------- Threefry-2x32-20, key = (0, 42) --------------------------
__device__ __forceinline__ void threefry2x32_42(unsigned c0, unsigned c1,
                                                unsigned& o0, unsigned& o1) {
    const unsigned ks0 = 0u;
    const unsigned ks1 = 42u;
    const unsigned ks2 = 0x1BD11BDAu ^ ks0 ^ ks1;
    unsigned x0 = c0 + ks0;
    unsigned x1 = c1 + ks1;
#define TF_ROUND(R) { x0 += x1; x1 = __funnelshift_l(x1, x1, (R)); x1 ^= x0; }
    TF_ROUND(13) TF_ROUND(15) TF_ROUND(26) TF_ROUND(6)
    x0 += ks1; x1 += ks2 + 1u;
    TF_ROUND(17) TF_ROUND(29) TF_ROUND(16) TF_ROUND(24)
    x0 += ks2; x1 += ks0 + 2u;
    TF_ROUND(13) TF_ROUND(15) TF_ROUND(26) TF_ROUND(6)
    x0 += ks0; x1 += ks1 + 3u;
    TF_ROUND(17) TF_ROUND(29) TF_ROUND(16) TF_ROUND(24)
    x0 += ks1; x1 += ks2 + 4u;
    TF_ROUND(13) TF_ROUND(15) TF_ROUND(26) TF_ROUND(6)
    x0 += ks2; x1 += ks0 + 5u;
#undef TF_ROUND
    o0 = x0; o1 = x1;
}

// jax uniform(tiny,1): f = bitcast((bits>>9)|0x3f800000)-1; u = max(f,tiny);
// gumbel = -log(-log(u)). Accurate logf (selection-critical near u->1).
__device__ __forceinline__ float gumbel_from_bits(unsigned bits) {
    const float tiny = 1.17549435e-38f;
    float f = __uint_as_float((bits >> 9) | 0x3f800000u) - 1.0f;
    float u = fmaxf(f, tiny);
    return -logf(-logf(u));
}

struct SmemP1 {
    float shA[32][33];
    float shB[32][33];
};
struct SmemP2 {
    int    s_lab[BB];
    int    buf_k[NWARP][BB];
    float  buf_d[NWARP][BB];
    float  buf_n[NWARP][BB];
    double s_wsum[NWARP];
    unsigned s_wcnt[NWARP];
    unsigned s_qstart;
    unsigned s_qend;
};

__global__ __launch_bounds__(256) void triplet_fused(const float* __restrict__ feat,
                                                     const int*   __restrict__ labels,
                                                     const int*   __restrict__ epoch_p,
                                                     float*       __restrict__ out) {
    __shared__ union { SmemP1 p1; SmemP2 p2; } sm;
    const int t    = threadIdx.x;
    const int wid  = t >> 5;
    const int lane = t & 31;

    // ---------------- phase 1a: enqueue valid (i,p) pairs ------------------
    for (int i = blockIdx.x; i < BB; i += GRID) {
        const int labi = labels[i];
        for (int p = i + 1 + t; p < BB; p += 256) {
            if (labels[p] == labi) {
                unsigned idx = atomicAdd(&g_qn, 1u);
                g_queue[idx & (QCAP - 1u)] = ((unsigned)i << 16) | (unsigned)p;
            }
        }
    }

    // ---------------- phase 1b: dist tile (32x32, 2x2 micro-tiles) ---------
    {
        const int bx = blockIdx.x % 12, by = blockIdx.x / 12;
        const int tx = t & 15, ty = t >> 4;
        const int i0 = by * 32, j0 = bx * 32;
        const int lr = t >> 3;
        const int lc = (t & 7) * 4;
        float a00 = 0.f, a01 = 0.f, a10 = 0.f, a11 = 0.f;

        for (int d0 = 0; d0 < DD; d0 += 32) {
            const float4 av = *(const float4*)&feat[(i0 + lr) * DD + d0 + lc];
            const float4 bv = *(const float4*)&feat[(j0 + lr) * DD + d0 + lc];
            sm.p1.shA[lr][lc + 0] = av.x; sm.p1.shA[lr][lc + 1] = av.y;
            sm.p1.shA[lr][lc + 2] = av.z; sm.p1.shA[lr][lc + 3] = av.w;
            sm.p1.shB[lr][lc + 0] = bv.x; sm.p1.shB[lr][lc + 1] = bv.y;
            sm.p1.shB[lr][lc + 2] = bv.z; sm.p1.shB[lr][lc + 3] = bv.w;
            __syncthreads();
#pragma unroll
            for (int kk = 0; kk < 32; ++kk) {
                const float ai0 = sm.p1.shA[2 * ty + 0][kk];
                const float ai1 = sm.p1.shA[2 * ty + 1][kk];
                const float bj0 = sm.p1.shB[2 * tx + 0][kk];
                const float bj1 = sm.p1.shB[2 * tx + 1][kk];
                float d;
                d = ai0 - bj0; a00 = fmaf(d, d, a00);
                d = ai0 - bj1; a01 = fmaf(d, d, a01);
                d = ai1 - bj0; a10 = fmaf(d, d, a10);
                d = ai1 - bj1; a11 = fmaf(d, d, a11);
            }
            __syncthreads();
        }
        const int i = i0 + 2 * ty;
        const int j = j0 + 2 * tx;
        const float d00 = sqrtf(fmaxf(a00, 1e-11f));
        const float d01 = sqrtf(fmaxf(a01, 1e-11f));
        const float d10 = sqrtf(fmaxf(a10, 1e-11f));
        const float d11 = sqrtf(fmaxf(a11, 1e-11f));
        g_dist[(i + 0) * BB + j + 0] = d00;  g_nld[(i + 0) * BB + j + 0] = -logf(d00);
        g_dist[(i + 0) * BB + j + 1] = d01;  g_nld[(i + 0) * BB + j + 1] = -logf(d01);
        g_dist[(i + 1) * BB + j + 0] = d10;  g_nld[(i + 1) * BB + j + 0] = -logf(d10);
        g_dist[(i + 1) * BB + j + 1] = d11;  g_nld[(i + 1) * BB + j + 1] = -logf(d11);
    }

    // ---------------- grid sync (generation counter; replay-safe) ----------
    __syncthreads();
    if (t == 0) {
        __threadfence();
        unsigned old = atomicAdd(&g_arrive, 1u);
        unsigned target = (old / (unsigned)GRID + 1u) * (unsigned)GRID;
        while (atomicAdd(&g_arrive, 0u) < target) __nanosleep(32);
        __threadfence();
    }
    __syncthreads();

    // ---------------- phase 2: warp-per-pair mining -------------------------
    const bool semiMode = (*epoch_p) > 3;

    // Queue bounds: ONE volatile load per block (all q writes happen-before
    // the fenced grid sync; volatile bypasses L1). NO per-thread atomics.
    if (t == 0) {
        sm.p2.s_qend   = *(volatile unsigned*)&g_qn;
        sm.p2.s_qstart = *(volatile unsigned*)&g_qbase;
    }
    for (int k = t; k < BB; k += 256) sm.p2.s_lab[k] = labels[k];
    __syncthreads();

    const unsigned qend   = sm.p2.s_qend;
    const unsigned qstart = sm.p2.s_qstart;
    const unsigned npairs = qend - qstart;

    double   lsum = 0.0;
    unsigned lcnt = 0u;
    const unsigned gw = (unsigned)blockIdx.x * NWARP + (unsigned)wid;

    for (unsigned off = gw; off < npairs; off += (unsigned)GRID * NWARP) {
        const unsigned q = g_queue[(qstart + off) & (QCAP - 1u)];
        const int i = (int)(q >> 16);
        const int p = (int)(q & 0xffffu);
        const float* __restrict__ drow = g_dist + i * BB;
        const float* __restrict__ nrow = g_nld  + i * BB;
        const int   labi = sm.p2.s_lab[i];
        const float dp   = drow[p];
        const float dhi  = dp + MARGIN;
        const unsigned nbase = ((unsigned)i * BB + (unsigned)p) * (unsigned)BB;

        // both rows into registers (MLP=24, all independent of dp)
        float dk[12], nk[12];
#pragma unroll
        for (int tile = 0; tile < 12; ++tile) {
            dk[tile] = drow[tile * 32 + lane];
            nk[tile] = nrow[tile * 32 + lane];
        }

        // mask scan + ballot compaction (ascending k order preserved)
        int cnt = 0;
#pragma unroll
        for (int tile = 0; tile < 12; ++tile) {
            const int k = tile * 32 + lane;
            bool s;
            if (semiMode) s = (sm.p2.s_lab[k] != labi) && (dk[tile] > dp) && (dk[tile] < dhi);
            else          s = (sm.p2.s_lab[k] != labi);
            const unsigned bal = __ballot_sync(0xffffffffu, s);
            if (s) {
                int pos = cnt + __popc(bal & ((1u << lane) - 1u));
                sm.p2.buf_k[wid][pos] = k;
                sm.p2.buf_d[wid][pos] = dk[tile];
                sm.p2.buf_n[wid][pos] = nk[tile];
            }
            cnt += __popc(bal);
        }

        // score compacted candidates (lane-strided ascending k:
        // strict '>' keeps first max per lane; no global loads in chain)
        float best = -3.4e38f;
        int   bk   = 0;
        float bd   = 0.0f;
        for (int c = lane; c < cnt; c += 32) {
            const int k = sm.p2.buf_k[wid][c];
            unsigned o0, o1;
            threefry2x32_42(0u, nbase + (unsigned)k, o0, o1);
            float sc = (semiMode ? sm.p2.buf_n[wid][c] : 0.0f)
                     + gumbel_from_bits(o0 ^ o1);
            if (sc > best) { best = sc; bk = k; bd = sm.p2.buf_d[wid][c]; }
        }
        // warp argmax, lowest-index tie-break (matches jnp.argmax)
#pragma unroll
        for (int o = 16; o > 0; o >>= 1) {
            float ov = __shfl_down_sync(0xffffffffu, best, o);
            int   ok = __shfl_down_sync(0xffffffffu, bk,   o);
            float od = __shfl_down_sync(0xffffffffu, bd,   o);
            if (ov > best || (ov == best && ok < bk)) { best = ov; bk = ok; bd = od; }
        }
        if (lane == 0 && cnt > 0) {
            lsum += (double)fmaxf(dp - bd + MARGIN, 0.0f);
            lcnt += 1u;
        }
    }

    // ---------------- block aggregation + last-done epilogue ---------------
    if (lane == 0) { sm.p2.s_wsum[wid] = lsum; sm.p2.s_wcnt[wid] = lcnt; }
    __syncthreads();
    if (t == 0) {
        double   bs = 0.0;
        unsigned bc = 0u;
#pragma unroll
        for (int w = 0; w < NWARP; ++w) { bs += sm.p2.s_wsum[w]; bc += sm.p2.s_wcnt[w]; }
        if (bc > 0u) {
            atomicAdd(&g_total, bs);
            atomicAdd(&g_count, bc);
        }
        __threadfence();
        unsigned old = atomicAdd(&g_done, 1u);
        if ((old % (unsigned)GRID) == (unsigned)GRID - 1u) {
            unsigned long long tb = atomicExch((unsigned long long*)&g_total, 0ull);
            double   tot = __longlong_as_double((long long)tb);
            unsigned cnt = atomicExch(&g_count, 0u);
            out[0] = (cnt > 0u) ? (float)(tot / (double)cnt) : 0.0f;
            atomicExch(&g_qbase, qend);      // next replay's queue start
        }
    }
}

extern "C" void kernel_launch(void* const* d_in, const int* in_sizes, int n_in,
                              void* d_out, int out_size) {
    const float* feat   = (const float*)d_in[0];
    const int*   labels = (const int*)d_in[1];
    const int*   epoch  = (const int*)d_in[2];
    float*       out    = (float*)d_out;

    triplet_fused<<<GRID, 256>>>(feat, labels, epoch, out);
}